// round 11
// baseline (speedup 1.0000x reference)
#include <cuda_runtime.h>
#include <cstddef>

// Problem constants
constexpr int NB  = 4;
constexpr int NS  = 2048;
constexpr int ND  = 1024;
constexpr int NH  = 16;
constexpr int NDK = 64;
constexpr int NBS = NB * NS;          // 8192

// Scratch (static device globals — no allocation)
__device__ float g_xr [(size_t)NBS * ND];                 // x, tf32-rounded
__device__ float g_wt [(size_t)NH * 3 * NDK * ND];        // [h*192+n][k], tf32
__device__ float g_wot[(size_t)ND * ND];                  // Wo^T [n][k], tf32
__device__ float g_q  [(size_t)NB * NH * NS * NDK];       // [B,H,S,DK]  tf32-rounded
__device__ float g_k  [(size_t)NB * NH * NS * NDK];       // [B,H,S,DK]  tf32-rounded
__device__ float g_vt [(size_t)NB * NH * NDK * NS];       // [B,H,DK,S]  tf32-rounded
__device__ float g_cat[(size_t)NBS * NH * NDK];           // [B*S, H*DK] tf32-rounded

// smem budgets (dynamic, opt-in via cudaFuncSetAttribute)
constexpr int GEMM_STAGE_F = 128 * 20;                    // floats per operand per stage
constexpr int GEMM_SMEM_B  = 3 * 2 * GEMM_STAGE_F * 4;    // 61440 bytes
constexpr int ATTN_KB_F = 2 * 32 * 68;                    // 4352
constexpr int ATTN_VB_F = 2 * 64 * 36;                    // 4608
constexpr int ATTN_PB_F = 128 * 36;                       // 4608
constexpr int ATTN_SMEM_B = (ATTN_KB_F + ATTN_VB_F + ATTN_PB_F) * 4;  // 54272

// ---------------------------------------------------------------------------
// helpers
// ---------------------------------------------------------------------------
__device__ __forceinline__ float f2tff(float f) {
    unsigned u;
    asm("cvt.rna.tf32.f32 %0, %1;" : "=r"(u) : "f"(f));
    return __uint_as_float(u);
}

__device__ __forceinline__ void mma8(float* c, const unsigned* a, const unsigned* b) {
    asm volatile(
        "mma.sync.aligned.m16n8k8.row.col.f32.tf32.tf32.f32 "
        "{%0,%1,%2,%3}, {%4,%5,%6,%7}, {%8,%9}, {%0,%1,%2,%3};"
        : "+f"(c[0]), "+f"(c[1]), "+f"(c[2]), "+f"(c[3])
        : "r"(a[0]), "r"(a[1]), "r"(a[2]), "r"(a[3]), "r"(b[0]), "r"(b[1]));
}

__device__ __forceinline__ void ldsm4(unsigned* r, const float* p) {
    unsigned a = (unsigned)__cvta_generic_to_shared(p);
    asm volatile("ldmatrix.sync.aligned.m8n8.x4.shared.b16 {%0,%1,%2,%3}, [%4];"
        : "=r"(r[0]), "=r"(r[1]), "=r"(r[2]), "=r"(r[3]) : "r"(a));
}

__device__ __forceinline__ void cpa16(float* dst, const float* src) {
    unsigned d = (unsigned)__cvta_generic_to_shared(dst);
    asm volatile("cp.async.cg.shared.global [%0], [%1], 16;" :: "r"(d), "l"(src));
}
#define CP_COMMIT() asm volatile("cp.async.commit_group;")
#define CP_WAIT0()  asm volatile("cp.async.wait_group 0;")
#define CP_WAIT1()  asm volatile("cp.async.wait_group 1;")

// ---------------------------------------------------------------------------
// Prep kernels
// ---------------------------------------------------------------------------
__global__ void round_x_kernel(const float* __restrict__ x) {
    size_t i = ((size_t)blockIdx.x * 256 + threadIdx.x) * 4;
    float4 v = *(const float4*)(x + i);
    *(float4*)(g_xr + i) =
        make_float4(f2tff(v.x), f2tff(v.y), f2tff(v.z), f2tff(v.w));
}

__global__ void pack_w_kernel(const float* __restrict__ Wq,
                              const float* __restrict__ Wk,
                              const float* __restrict__ Wv) {
    __shared__ float t[32][33];
    int mat = blockIdx.z % 3, h = blockIdx.z / 3;
    const float* W = (mat == 0) ? Wq : (mat == 1) ? Wk : Wv;
    const float* src = W + (size_t)h * ND * NDK;
    int k0 = blockIdx.x * 32, n0 = blockIdx.y * 32;
    int tx = threadIdx.x, ty = threadIdx.y;
    #pragma unroll
    for (int i = 0; i < 4; i++)
        t[ty + 8 * i][tx] = src[(size_t)(k0 + ty + 8 * i) * NDK + n0 + tx];
    __syncthreads();
    float* dst = g_wt + ((size_t)h * 192 + mat * 64) * ND;
    #pragma unroll
    for (int i = 0; i < 4; i++)
        dst[(size_t)(n0 + ty + 8 * i) * ND + k0 + tx] = f2tff(t[tx][ty + 8 * i]);
}

__global__ void pack_wo_kernel(const float* __restrict__ Wo) {
    __shared__ float t[32][33];
    int k0 = blockIdx.x * 32, n0 = blockIdx.y * 32;
    int tx = threadIdx.x, ty = threadIdx.y;
    #pragma unroll
    for (int i = 0; i < 4; i++)
        t[ty + 8 * i][tx] = Wo[(size_t)(k0 + ty + 8 * i) * ND + n0 + tx];
    __syncthreads();
    #pragma unroll
    for (int i = 0; i < 4; i++)
        g_wot[(size_t)(n0 + ty + 8 * i) * ND + k0 + tx] = f2tff(t[tx][ty + 8 * i]);
}

// ---------------------------------------------------------------------------
// Shared GEMM mainloop body (qkv & proj): 128x128 tile, BK=16, 3-stage
// cp.async pipeline, 1 barrier/iter. 8 warps 4(m)x2(n) -> warp 32x64.
// ---------------------------------------------------------------------------
struct GemmCtx {
    float* As; float* Bs;
    const float* xb; const float* wb;
    int sr, sc, aoff, boff, wm, wn;
};

__device__ __forceinline__ void gemm_stage(const GemmCtx& c, int st) {
    int buf = (st % 3) * GEMM_STAGE_F;
    int kk = st * 16;
    cpa16(&c.As[buf + c.sr * 20 + c.sc],        c.xb + (size_t)c.sr * ND + kk + c.sc);
    cpa16(&c.As[buf + (c.sr + 64) * 20 + c.sc], c.xb + (size_t)(c.sr + 64) * ND + kk + c.sc);
    cpa16(&c.Bs[buf + c.sr * 20 + c.sc],        c.wb + (size_t)c.sr * ND + kk + c.sc);
    cpa16(&c.Bs[buf + (c.sr + 64) * 20 + c.sc], c.wb + (size_t)(c.sr + 64) * ND + kk + c.sc);
}

__device__ __forceinline__ void gemm_mainloop(const GemmCtx& c, float acc[2][8][4]) {
    constexpr int NIT = ND / 16;   // 64
    gemm_stage(c, 0); CP_COMMIT();
    gemm_stage(c, 1); CP_COMMIT();
    for (int i = 0; i < NIT; i++) {
        if (i + 1 < NIT) { CP_WAIT1(); } else { CP_WAIT0(); }
        __syncthreads();           // stage i visible; all warps done with i-1
        if (i + 2 < NIT) { gemm_stage(c, i + 2); CP_COMMIT(); }
        const float* AsW = c.As + (i % 3) * GEMM_STAGE_F + (c.wm * 32) * 20;
        const float* BsW = c.Bs + (i % 3) * GEMM_STAGE_F + (c.wn * 64) * 20;
        #pragma unroll
        for (int ks = 0; ks < 2; ks++) {
            unsigned a[2][4];
            ldsm4(a[0], AsW + c.aoff + ks * 8);
            ldsm4(a[1], AsW + 16 * 20 + c.aoff + ks * 8);
            #pragma unroll
            for (int np = 0; np < 4; np++) {
                unsigned b4[4];
                ldsm4(b4, BsW + np * 16 * 20 + c.boff + ks * 8);
                mma8(acc[0][2 * np],     a[0], &b4[0]);
                mma8(acc[0][2 * np + 1], a[0], &b4[2]);
                mma8(acc[1][2 * np],     a[1], &b4[0]);
                mma8(acc[1][2 * np + 1], a[1], &b4[2]);
            }
        }
    }
}

// ---------------------------------------------------------------------------
// Kernel 1: fused QKV projection. C[8192, 3072] = xr @ g_wt^T (+bias routing).
// ---------------------------------------------------------------------------
__global__ __launch_bounds__(256, 2) void qkv_kernel(
    const float* __restrict__ bq, const float* __restrict__ bk,
    const float* __restrict__ bv)
{
    extern __shared__ __align__(16) float sm[];
    const int m0 = blockIdx.x * 128;
    const int n0 = blockIdx.y * 128;
    const int tid  = threadIdx.x;
    const int warp = tid >> 5, lane = tid & 31;
    const int g = lane >> 2, tg = lane & 3;

    GemmCtx c;
    c.As = sm; c.Bs = sm + 3 * GEMM_STAGE_F;
    c.xb = g_xr + (size_t)m0 * ND;
    c.wb = g_wt + (size_t)n0 * ND;
    c.sr = tid >> 2; c.sc = (tid & 3) * 4;
    c.aoff = (lane & 15) * 20 + (lane >> 4) * 4;
    c.boff = ((lane >> 4) * 8 + (lane & 7)) * 20 + ((lane >> 3) & 1) * 4;
    c.wm = warp >> 1; c.wn = warp & 1;

    float acc[2][8][4] = {};
    gemm_mainloop(c, acc);

    // Epilogue: + bias, tf32-round, route q/k row-major, v transposed
    #pragma unroll
    for (int nt = 0; nt < 8; nt++) {
        int n_g = n0 + c.wn * 64 + nt * 8 + 2 * tg;
        int h = n_g / 192, wh = n_g % 192;
        int mat = wh >> 6, cm = wh & 63;
        const float* bp = (mat == 0) ? bq : (mat == 1) ? bk : bv;
        float b0v = bp[h * NDK + cm], b1v = bp[h * NDK + cm + 1];
        #pragma unroll
        for (int mt = 0; mt < 2; mt++)
            #pragma unroll
            for (int p = 0; p < 2; p++) {
                int m = m0 + c.wm * 32 + mt * 16 + g + p * 8;
                int b_ = m >> 11, s = m & 2047;
                int bh = b_ * NH + h;
                float v0 = f2tff(acc[mt][nt][2 * p + 0] + b0v);
                float v1 = f2tff(acc[mt][nt][2 * p + 1] + b1v);
                if (mat < 2) {
                    float* dst = ((mat == 0) ? g_q : g_k) + (size_t)bh * NS * NDK;
                    *(float2*)(dst + (size_t)s * NDK + cm) = make_float2(v0, v1);
                } else {
                    float* vt = g_vt + (size_t)bh * NDK * NS;
                    vt[(size_t)cm       * NS + s] = v0;
                    vt[(size_t)(cm + 1) * NS + s] = v1;
                }
            }
    }
}

// ---------------------------------------------------------------------------
// Kernel 2: causal flash attention. 256 threads (8 warps), Q tile 128 rows
// (16/warp, frags in regs), 32-key tiles double-buffered via cp.async.
// Kb: 2x(32x68), Vb: 2x(64x36) [feat][key], Pb: 128x36 (warp-private rows).
// ---------------------------------------------------------------------------
__global__ __launch_bounds__(256, 2) void attn_kernel()
{
    extern __shared__ __align__(16) float sm[];
    float* Kb = sm;                      // 2*32*68 (also Q staging: 64x68)
    float* Vb = sm + ATTN_KB_F;
    float* Pb = sm + ATTN_KB_F + ATTN_VB_F;

    const int qt = (int)(gridDim.x - 1) - (int)blockIdx.x;  // heavy first
    const int bh = blockIdx.y;
    const int q0 = qt * 128;
    const float* qb  = g_q  + (size_t)bh * NS * NDK;
    const float* kb  = g_k  + (size_t)bh * NS * NDK;
    const float* vtb = g_vt + (size_t)bh * NDK * NS;

    const int tid = threadIdx.x;
    const int w = tid >> 5, lane = tid & 31;
    const int g = lane >> 2, tg = lane & 3;

    const int aoff68 = (lane & 15) * 68 + (lane >> 4) * 4;
    const int boff68 = ((lane >> 4) * 8 + (lane & 7)) * 68 + ((lane >> 3) & 1) * 4;
    const int aoff36 = (lane & 15) * 36 + (lane >> 4) * 4;
    const int boff36 = ((lane >> 4) * 8 + (lane & 7)) * 36 + ((lane >> 3) & 1) * 4;

    // Stage Q 128x64 in two 64-row passes through Kb; each half's warps grab frags
    unsigned qa[8][4];
    #pragma unroll
    for (int half = 0; half < 2; half++) {
        #pragma unroll
        for (int t = 0; t < 4; t++) {
            int f = tid + t * 256;
            int r = f >> 4, c4 = (f & 15) * 4;
            *(float4*)&Kb[r * 68 + c4] =
                *(const float4*)(qb + (size_t)(q0 + half * 64 + r) * NDK + c4);
        }
        __syncthreads();
        if ((w >> 2) == half) {
            int wl = w & 3;
            #pragma unroll
            for (int ks = 0; ks < 8; ks++)
                ldsm4(qa[ks], Kb + (wl * 16) * 68 + aoff68 + ks * 8);
        }
        __syncthreads();   // frag loads done before next overwrite
    }

    // preload KV tile 0
    #pragma unroll
    for (int t = 0; t < 2; t++) {
        int f = tid + t * 256;
        int r = f >> 4, c4 = (f & 15) * 4;
        cpa16(&Kb[r * 68 + c4], kb + (size_t)r * NDK + c4);
    }
    #pragma unroll
    for (int t = 0; t < 2; t++) {
        int f = tid + t * 256;
        int r = f >> 3, c4 = (f & 7) * 4;
        cpa16(&Vb[r * 36 + c4], vtb + (size_t)r * NS + c4);
    }
    CP_COMMIT();

    float oacc[8][4] = {};
    float m_i[2] = {-3.0e38f, -3.0e38f};
    float l_i[2] = {0.f, 0.f};

    const int nkt = 4 * qt + 4;     // 32-key tiles covering [0, q0+128)
    for (int jt = 0; jt < nkt; jt++) {
        CP_WAIT0();
        __syncthreads();   // tile jt landed; all warps done with jt-1
        if (jt + 1 < nkt) {
            int kbuf = ((jt + 1) & 1) * (32 * 68);
            int vbuf = ((jt + 1) & 1) * (64 * 36);
            int kc0n = (jt + 1) * 32;
            #pragma unroll
            for (int t = 0; t < 2; t++) {
                int f = tid + t * 256;
                int r = f >> 4, c4 = (f & 15) * 4;
                cpa16(&Kb[kbuf + r * 68 + c4], kb + (size_t)(kc0n + r) * NDK + c4);
            }
            #pragma unroll
            for (int t = 0; t < 2; t++) {
                int f = tid + t * 256;
                int r = f >> 3, c4 = (f & 7) * 4;
                cpa16(&Vb[vbuf + r * 36 + c4], vtb + (size_t)r * NS + kc0n + c4);
            }
            CP_COMMIT();
        }
        const float* Kt = Kb + (jt & 1) * (32 * 68);
        const float* Vt = Vb + (jt & 1) * (64 * 36);
        const int kc0 = jt * 32;

        // S = Q K^T  (warp: 16 x 32)
        float sacc[4][4] = {};
        #pragma unroll
        for (int ks = 0; ks < 8; ks++) {
            #pragma unroll
            for (int np = 0; np < 2; np++) {
                unsigned kb4[4];
                ldsm4(kb4, Kt + np * 16 * 68 + boff68 + ks * 8);
                mma8(sacc[2 * np],     qa[ks], &kb4[0]);
                mma8(sacc[2 * np + 1], qa[ks], &kb4[2]);
            }
        }

        // scale + causal mask (last 4 tiles touch the diagonal band)
        const int r0 = q0 + w * 16 + g;
        if (jt >= nkt - 4) {
            #pragma unroll
            for (int nt = 0; nt < 4; nt++) {
                int col = kc0 + nt * 8 + 2 * tg;
                sacc[nt][0] = (col     <= r0    ) ? sacc[nt][0] * 0.125f : -3.0e38f;
                sacc[nt][1] = (col + 1 <= r0    ) ? sacc[nt][1] * 0.125f : -3.0e38f;
                sacc[nt][2] = (col     <= r0 + 8) ? sacc[nt][2] * 0.125f : -3.0e38f;
                sacc[nt][3] = (col + 1 <= r0 + 8) ? sacc[nt][3] * 0.125f : -3.0e38f;
            }
        } else {
            #pragma unroll
            for (int nt = 0; nt < 4; nt++) {
                sacc[nt][0] *= 0.125f; sacc[nt][1] *= 0.125f;
                sacc[nt][2] *= 0.125f; sacc[nt][3] *= 0.125f;
            }
        }

        // row max
        float mt0 = -3.0e38f, mt1 = -3.0e38f;
        #pragma unroll
        for (int nt = 0; nt < 4; nt++) {
            mt0 = fmaxf(mt0, fmaxf(sacc[nt][0], sacc[nt][1]));
            mt1 = fmaxf(mt1, fmaxf(sacc[nt][2], sacc[nt][3]));
        }
        mt0 = fmaxf(mt0, __shfl_xor_sync(0xffffffffu, mt0, 1));
        mt0 = fmaxf(mt0, __shfl_xor_sync(0xffffffffu, mt0, 2));
        mt1 = fmaxf(mt1, __shfl_xor_sync(0xffffffffu, mt1, 1));
        mt1 = fmaxf(mt1, __shfl_xor_sync(0xffffffffu, mt1, 2));

        float mn0 = fmaxf(m_i[0], mt0), mn1 = fmaxf(m_i[1], mt1);
        float al0 = __expf(m_i[0] - mn0), al1 = __expf(m_i[1] - mn1);
        m_i[0] = mn0; m_i[1] = mn1;

        const int rb0 = (w * 16 + g) * 36;
        const int rb1 = rb0 + 8 * 36;
        float ls0 = 0.f, ls1 = 0.f;
        #pragma unroll
        for (int nt = 0; nt < 4; nt++) {
            float p0 = __expf(sacc[nt][0] - mn0);
            float p1 = __expf(sacc[nt][1] - mn0);
            float p2 = __expf(sacc[nt][2] - mn1);
            float p3 = __expf(sacc[nt][3] - mn1);
            ls0 += p0 + p1; ls1 += p2 + p3;
            int cl = nt * 8 + 2 * tg;
            *(float2*)&Pb[rb0 + cl] = make_float2(f2tff(p0), f2tff(p1));
            *(float2*)&Pb[rb1 + cl] = make_float2(f2tff(p2), f2tff(p3));
        }
        #pragma unroll
        for (int nt = 0; nt < 8; nt++) {
            oacc[nt][0] *= al0; oacc[nt][1] *= al0;
            oacc[nt][2] *= al1; oacc[nt][3] *= al1;
        }
        ls0 += __shfl_xor_sync(0xffffffffu, ls0, 1);
        ls0 += __shfl_xor_sync(0xffffffffu, ls0, 2);
        ls1 += __shfl_xor_sync(0xffffffffu, ls1, 1);
        ls1 += __shfl_xor_sync(0xffffffffu, ls1, 2);
        l_i[0] = l_i[0] * al0 + ls0;
        l_i[1] = l_i[1] * al1 + ls1;

        __syncwarp();      // P rows warp-private

        // O += P @ V  (warp: 16 x 64, k = 32 keys)
        #pragma unroll
        for (int ks = 0; ks < 4; ks++) {
            unsigned pa[4];
            ldsm4(pa, Pb + (w * 16) * 36 + aoff36 + ks * 8);
            #pragma unroll
            for (int np = 0; np < 4; np++) {
                unsigned vb4[4];
                ldsm4(vb4, Vt + np * 16 * 36 + boff36 + ks * 8);
                mma8(oacc[2 * np],     pa, &vb4[0]);
                mma8(oacc[2 * np + 1], pa, &vb4[2]);
            }
        }
    }

    // normalize + tf32-round + write concat layout [B*S, H*DK]
    const float inv0 = 1.f / l_i[0], inv1 = 1.f / l_i[1];
    const int b_ = bh / NH, h_ = bh % NH;
    const size_t mrow = (size_t)b_ * NS + q0 + w * 16 + g;
    #pragma unroll
    for (int nt = 0; nt < 8; nt++) {
        int cc = h_ * NDK + nt * 8 + 2 * tg;
        *(float2*)&g_cat[ mrow      * (NH * NDK) + cc] =
            make_float2(f2tff(oacc[nt][0] * inv0), f2tff(oacc[nt][1] * inv0));
        *(float2*)&g_cat[(mrow + 8) * (NH * NDK) + cc] =
            make_float2(f2tff(oacc[nt][2] * inv1), f2tff(oacc[nt][3] * inv1));
    }
}

// ---------------------------------------------------------------------------
// Kernel 3: output projection. C[8192,1024] = g_cat @ Wo + bo.
// ---------------------------------------------------------------------------
__global__ __launch_bounds__(256, 2) void proj_kernel(
    const float* __restrict__ bo, float* __restrict__ out)
{
    extern __shared__ __align__(16) float sm[];
    const int m0 = blockIdx.y * 128;
    const int n0 = blockIdx.x * 128;
    const int tid  = threadIdx.x;
    const int warp = tid >> 5, lane = tid & 31;
    const int g = lane >> 2, tg = lane & 3;

    GemmCtx c;
    c.As = sm; c.Bs = sm + 3 * GEMM_STAGE_F;
    c.xb = g_cat + (size_t)m0 * ND;
    c.wb = g_wot + (size_t)n0 * ND;
    c.sr = tid >> 2; c.sc = (tid & 3) * 4;
    c.aoff = (lane & 15) * 20 + (lane >> 4) * 4;
    c.boff = ((lane >> 4) * 8 + (lane & 7)) * 20 + ((lane >> 3) & 1) * 4;
    c.wm = warp >> 1; c.wn = warp & 1;

    float acc[2][8][4] = {};
    gemm_mainloop(c, acc);

    // Epilogue (final output fp32, no rounding)
    #pragma unroll
    for (int nt = 0; nt < 8; nt++) {
        int cc = c.wn * 64 + nt * 8 + 2 * tg;
        float b0 = bo[n0 + cc], b1 = bo[n0 + cc + 1];
        #pragma unroll
        for (int mt = 0; mt < 2; mt++)
            #pragma unroll
            for (int p = 0; p < 2; p++) {
                int rr = c.wm * 32 + mt * 16 + g + p * 8;
                float2 v;
                v.x = acc[mt][nt][2 * p + 0] + b0;
                v.y = acc[mt][nt][2 * p + 1] + b1;
                *(float2*)(out + (size_t)(m0 + rr) * ND + n0 + cc) = v;
            }
    }
}

// ---------------------------------------------------------------------------
extern "C" void kernel_launch(void* const* d_in, const int* in_sizes, int n_in,
                              void* d_out, int out_size)
{
    (void)in_sizes; (void)n_in; (void)out_size;
    const float* x  = (const float*)d_in[0];
    // d_in[1] = encoder_output (unused in the self-attention path)
    const float* Wq = (const float*)d_in[2];
    const float* bq = (const float*)d_in[3];
    const float* Wk = (const float*)d_in[4];
    const float* bk = (const float*)d_in[5];
    const float* Wv = (const float*)d_in[6];
    const float* bv = (const float*)d_in[7];
    const float* Wo = (const float*)d_in[8];
    const float* bo = (const float*)d_in[9];
    float* out = (float*)d_out;

    // Opt-in dynamic smem limits (attribute set; not an allocation). Idempotent.
    cudaFuncSetAttribute(qkv_kernel,  cudaFuncAttributeMaxDynamicSharedMemorySize, GEMM_SMEM_B);
    cudaFuncSetAttribute(attn_kernel, cudaFuncAttributeMaxDynamicSharedMemorySize, ATTN_SMEM_B);
    cudaFuncSetAttribute(proj_kernel, cudaFuncAttributeMaxDynamicSharedMemorySize, GEMM_SMEM_B);

    round_x_kernel<<<(NBS * ND) / (256 * 4), 256>>>(x);
    pack_w_kernel<<<dim3(ND / 32, NDK / 32, NH * 3), dim3(32, 8)>>>(Wq, Wk, Wv);
    pack_wo_kernel<<<dim3(ND / 32, ND / 32), dim3(32, 8)>>>(Wo);
    qkv_kernel<<<dim3(NBS / 128, (NH * 3 * NDK) / 128), 256, GEMM_SMEM_B>>>(bq, bk, bv);
    attn_kernel<<<dim3(NS / 128, NB * NH), 256, ATTN_SMEM_B>>>();
    proj_kernel<<<dim3(ND / 128, NBS / 128), 256, GEMM_SMEM_B>>>(bo, out);
}

// round 16
// speedup vs baseline: 1.7856x; 1.7856x over previous
#include <cuda_runtime.h>
#include <cuda_fp16.h>
#include <cstddef>
#include <cstdint>

// Problem constants
constexpr int NB  = 4;
constexpr int NS  = 2048;
constexpr int ND  = 1024;
constexpr int NH  = 16;
constexpr int NDK = 64;
constexpr int NBS = NB * NS;          // 8192

// Scratch (static device globals — no allocation), all fp16 operands
__device__ __align__(16) __half g_xh [(size_t)NBS * ND];            // x, fp16
__device__ __align__(16) __half g_wt [(size_t)NH * 3 * NDK * ND];   // [h*192+n][k]
__device__ __align__(16) __half g_wot[(size_t)ND * ND];             // Wo^T [n][k]
__device__ __align__(16) __half g_q  [(size_t)NB * NH * NS * NDK];  // [B,H,S,DK]
__device__ __align__(16) __half g_k  [(size_t)NB * NH * NS * NDK];  // [B,H,S,DK]
__device__ __align__(16) __half g_vt [(size_t)NB * NH * NDK * NS];  // [B,H,DK,S]
__device__ __align__(16) __half g_cat[(size_t)NBS * NH * NDK];      // [B*S, H*DK]

// ---------------------------------------------------------------------------
// helpers
// ---------------------------------------------------------------------------
// D += A(16x16,row) * B(16x8,col), fp16 inputs, fp32 accum
__device__ __forceinline__ void mma16(float* c, const unsigned* a, const unsigned* b) {
    asm volatile(
        "mma.sync.aligned.m16n8k16.row.col.f32.f16.f16.f32 "
        "{%0,%1,%2,%3}, {%4,%5,%6,%7}, {%8,%9}, {%0,%1,%2,%3};"
        : "+f"(c[0]), "+f"(c[1]), "+f"(c[2]), "+f"(c[3])
        : "r"(a[0]), "r"(a[1]), "r"(a[2]), "r"(a[3]), "r"(b[0]), "r"(b[1]));
}

__device__ __forceinline__ void ldsm4h(unsigned* r, const __half* p) {
    unsigned a = (unsigned)__cvta_generic_to_shared(p);
    asm volatile("ldmatrix.sync.aligned.m8n8.x4.shared.b16 {%0,%1,%2,%3}, [%4];"
        : "=r"(r[0]), "=r"(r[1]), "=r"(r[2]), "=r"(r[3]) : "r"(a));
}

__device__ __forceinline__ void cpa16h(__half* dst, const __half* src) {
    unsigned d = (unsigned)__cvta_generic_to_shared(dst);
    asm volatile("cp.async.cg.shared.global [%0], [%1], 16;" :: "r"(d), "l"(src));
}
#define CP_COMMIT() asm volatile("cp.async.commit_group;")
#define CP_WAIT0()  asm volatile("cp.async.wait_group 0;")

// ---------------------------------------------------------------------------
// Prep kernels: fp32 inputs -> fp16 packed operands
// ---------------------------------------------------------------------------
__global__ void conv_x_kernel(const float* __restrict__ x) {
    size_t i = ((size_t)blockIdx.x * 256 + threadIdx.x) * 8;
    float4 v0 = *(const float4*)(x + i);
    float4 v1 = *(const float4*)(x + i + 4);
    __half2 h[4];
    h[0] = __floats2half2_rn(v0.x, v0.y);
    h[1] = __floats2half2_rn(v0.z, v0.w);
    h[2] = __floats2half2_rn(v1.x, v1.y);
    h[3] = __floats2half2_rn(v1.z, v1.w);
    *(float4*)(g_xh + i) = *(float4*)h;
}

// Wq/Wk/Wv [H][1024][64] -> g_wt [h*192 + mat*64 + n][1024] (transposed, fp16)
__global__ void pack_w_kernel(const float* __restrict__ Wq,
                              const float* __restrict__ Wk,
                              const float* __restrict__ Wv) {
    __shared__ float t[32][33];
    int mat = blockIdx.z % 3, h = blockIdx.z / 3;
    const float* W = (mat == 0) ? Wq : (mat == 1) ? Wk : Wv;
    const float* src = W + (size_t)h * ND * NDK;
    int k0 = blockIdx.x * 32, n0 = blockIdx.y * 32;
    int tx = threadIdx.x, ty = threadIdx.y;
    #pragma unroll
    for (int i = 0; i < 4; i++)
        t[ty + 8 * i][tx] = src[(size_t)(k0 + ty + 8 * i) * NDK + n0 + tx];
    __syncthreads();
    __half* dst = g_wt + ((size_t)h * 192 + mat * 64) * ND;
    #pragma unroll
    for (int i = 0; i < 4; i++)
        dst[(size_t)(n0 + ty + 8 * i) * ND + k0 + tx] = __float2half_rn(t[tx][ty + 8 * i]);
}

__global__ void pack_wo_kernel(const float* __restrict__ Wo) {
    __shared__ float t[32][33];
    int k0 = blockIdx.x * 32, n0 = blockIdx.y * 32;
    int tx = threadIdx.x, ty = threadIdx.y;
    #pragma unroll
    for (int i = 0; i < 4; i++)
        t[ty + 8 * i][tx] = Wo[(size_t)(k0 + ty + 8 * i) * ND + n0 + tx];
    __syncthreads();
    #pragma unroll
    for (int i = 0; i < 4; i++)
        g_wot[(size_t)(n0 + ty + 8 * i) * ND + k0 + tx] = __float2half_rn(t[tx][ty + 8 * i]);
}

// ---------------------------------------------------------------------------
// fp16 GEMM mainloop (qkv & proj): 128x128 tile, BK=64, double-buffered
// cp.async, 1 barrier/iter. 8 warps 4(m)x2(n) -> warp 32x64. Pitch 72 halves
// (row 16B-groups stride 9 mod 8 = 1 -> all 8 bank-groups distinct).
// ---------------------------------------------------------------------------
constexpr int HP  = 72;               // pitch (halves)
constexpr int HST = 128 * HP;         // halves per operand per stage
constexpr int GEMM_SMEM_B = 2 * 2 * HST * 2;   // 73728 bytes

struct HGemmCtx {
    __half* As; __half* Bs;
    const __half* xb; const __half* wb;
    int aoff, wm, wn, tid;
};

__device__ __forceinline__ void h_stage(const HGemmCtx& c, int st) {
    __half* Ad = c.As + (st & 1) * HST;
    __half* Bd = c.Bs + (st & 1) * HST;
    const int kk = st * 64;
    #pragma unroll
    for (int t = 0; t < 4; t++) {
        int ci = c.tid + t * 256;
        int r = ci >> 3, cc = (ci & 7) * 8;
        cpa16h(Ad + r * HP + cc, c.xb + (size_t)r * ND + kk + cc);
    }
    #pragma unroll
    for (int t = 0; t < 4; t++) {
        int ci = c.tid + t * 256;
        int r = ci >> 3, cc = (ci & 7) * 8;
        cpa16h(Bd + r * HP + cc, c.wb + (size_t)r * ND + kk + cc);
    }
    CP_COMMIT();
}

__device__ __forceinline__ void h_mainloop(const HGemmCtx& c, float acc[2][8][4]) {
    constexpr int NIT = ND / 64;      // 16
    h_stage(c, 0);
    for (int i = 0; i < NIT; i++) {
        CP_WAIT0();
        __syncthreads();              // stage i visible; all warps done with i-1
        if (i + 1 < NIT) h_stage(c, i + 1);
        const __half* AsW = c.As + (i & 1) * HST + (c.wm * 32) * HP;
        const __half* BsW = c.Bs + (i & 1) * HST + (c.wn * 64) * HP;
        #pragma unroll
        for (int ks = 0; ks < 4; ks++) {
            unsigned a[2][4];
            ldsm4h(a[0], AsW + c.aoff + ks * 16);
            ldsm4h(a[1], AsW + 16 * HP + c.aoff + ks * 16);
            #pragma unroll
            for (int kp = 0; kp < 4; kp++) {
                unsigned b4[4];
                ldsm4h(b4, BsW + kp * 16 * HP + c.aoff + ks * 16);
                unsigned b0[2] = {b4[0], b4[2]};
                unsigned b1[2] = {b4[1], b4[3]};
                mma16(acc[0][kp * 2],     a[0], b0);
                mma16(acc[0][kp * 2 + 1], a[0], b1);
                mma16(acc[1][kp * 2],     a[1], b0);
                mma16(acc[1][kp * 2 + 1], a[1], b1);
            }
        }
    }
}

// ---------------------------------------------------------------------------
// Kernel 1: fused QKV projection. C[8192,3072] = xh @ g_wt^T (+bias routing).
// ---------------------------------------------------------------------------
__global__ __launch_bounds__(256, 2) void qkv_kernel(
    const float* __restrict__ bq, const float* __restrict__ bk,
    const float* __restrict__ bv)
{
    extern __shared__ __align__(16) __half smh[];
    const int m0 = blockIdx.x * 128;
    const int n0 = blockIdx.y * 128;
    const int tid  = threadIdx.x;
    const int warp = tid >> 5, lane = tid & 31;
    const int g = lane >> 2, tg = lane & 3;

    HGemmCtx c;
    c.As = smh; c.Bs = smh + 2 * HST;
    c.xb = g_xh + (size_t)m0 * ND;
    c.wb = g_wt + (size_t)n0 * ND;
    c.aoff = (lane & 15) * HP + (lane >> 4) * 8;
    c.wm = warp >> 1; c.wn = warp & 1; c.tid = tid;

    float acc[2][8][4] = {};
    h_mainloop(c, acc);

    // Epilogue: + bias (fp32), convert to fp16, route q/k row-major, v transposed
    #pragma unroll
    for (int nt = 0; nt < 8; nt++) {
        int n_g = n0 + c.wn * 64 + nt * 8 + 2 * tg;
        int h = n_g / 192, wh = n_g % 192;
        int mat = wh >> 6, cm = wh & 63;
        const float* bp = (mat == 0) ? bq : (mat == 1) ? bk : bv;
        float b0v = bp[h * NDK + cm], b1v = bp[h * NDK + cm + 1];
        #pragma unroll
        for (int mt = 0; mt < 2; mt++)
            #pragma unroll
            for (int p = 0; p < 2; p++) {
                int m = m0 + c.wm * 32 + mt * 16 + g + p * 8;
                int b_ = m >> 11, s = m & 2047;
                int bh = b_ * NH + h;
                float v0 = acc[mt][nt][2 * p + 0] + b0v;
                float v1 = acc[mt][nt][2 * p + 1] + b1v;
                if (mat < 2) {
                    __half* dst = ((mat == 0) ? g_q : g_k) + (size_t)bh * NS * NDK;
                    *(__half2*)(dst + (size_t)s * NDK + cm) = __floats2half2_rn(v0, v1);
                } else {
                    __half* vt = g_vt + (size_t)bh * NDK * NS;
                    vt[(size_t)cm       * NS + s] = __float2half_rn(v0);
                    vt[(size_t)(cm + 1) * NS + s] = __float2half_rn(v1);
                }
            }
    }
}

// ---------------------------------------------------------------------------
// Kernel 2: causal flash attention, fp16 MMA. 128 threads (4 warps),
// Q tile 64 rows (frags in regs), 32-key tiles double-buffered via cp.async.
// Kb pitch 72 (also Q staging), Vb [feat][key] pitch 40, Pb pitch 40.
// ---------------------------------------------------------------------------
constexpr int KP2 = 72;   // K/Q pitch (halves)
constexpr int VP2 = 40;   // V/P pitch (halves)

__global__ __launch_bounds__(128) void attn_kernel()
{
    __shared__ __align__(16) __half Kb[2 * 32 * KP2];   // Q staging uses both bufs
    __shared__ __align__(16) __half Vb[2 * 64 * VP2];
    __shared__ __align__(16) __half Pb[64 * VP2];

    const int qt = (int)(gridDim.x - 1) - (int)blockIdx.x;  // heavy first
    const int bh = blockIdx.y;
    const int q0 = qt * 64;
    const __half* qb  = g_q  + (size_t)bh * NS * NDK;
    const __half* kb  = g_k  + (size_t)bh * NS * NDK;
    const __half* vtb = g_vt + (size_t)bh * NDK * NS;

    const int tid = threadIdx.x;
    const int w = tid >> 5, lane = tid & 31;
    const int g = lane >> 2, tg = lane & 3;

    const int aoffK = (lane & 15) * KP2 + (lane >> 4) * 8;
    const int aoffV = (lane & 15) * VP2 + (lane >> 4) * 8;

    // Stage Q 64x64 halves across both Kb buffers (pitch 72)
    #pragma unroll
    for (int t = 0; t < 4; t++) {
        int ci = tid + t * 128;
        int r = ci >> 3, c4 = (ci & 7) * 8;
        *(float4*)&Kb[r * KP2 + c4] = *(const float4*)(qb + (size_t)(q0 + r) * NDK + c4);
    }
    __syncthreads();
    unsigned qa[4][4];
    #pragma unroll
    for (int ks = 0; ks < 4; ks++)
        ldsm4h(qa[ks], Kb + (w * 16) * KP2 + aoffK + ks * 16);
    __syncthreads();   // qa loads done before cp.async overwrites Kb

    // preload KV tile 0: K 32x64 (256 16B-chunks), V 64x32 (256 chunks)
    #pragma unroll
    for (int t = 0; t < 2; t++) {
        int ci = tid + t * 128;
        int r = ci >> 3, c4 = (ci & 7) * 8;
        cpa16h(&Kb[r * KP2 + c4], kb + (size_t)r * NDK + c4);
    }
    #pragma unroll
    for (int t = 0; t < 2; t++) {
        int ci = tid + t * 128;
        int r = ci >> 2, c4 = (ci & 3) * 8;
        cpa16h(&Vb[r * VP2 + c4], vtb + (size_t)r * NS + c4);
    }
    CP_COMMIT();

    float oacc[8][4] = {};
    float m_i[2] = {-3.0e38f, -3.0e38f};
    float l_i[2] = {0.f, 0.f};

    const int nkt = 2 * qt + 2;
    for (int jt = 0; jt < nkt; jt++) {
        CP_WAIT0();
        __syncthreads();   // tile jt landed; all warps done with jt-1
        if (jt + 1 < nkt) {
            __half* Kd = Kb + ((jt + 1) & 1) * (32 * KP2);
            __half* Vd = Vb + ((jt + 1) & 1) * (64 * VP2);
            int kc0n = (jt + 1) * 32;
            #pragma unroll
            for (int t = 0; t < 2; t++) {
                int ci = tid + t * 128;
                int r = ci >> 3, c4 = (ci & 7) * 8;
                cpa16h(Kd + r * KP2 + c4, kb + (size_t)(kc0n + r) * NDK + c4);
            }
            #pragma unroll
            for (int t = 0; t < 2; t++) {
                int ci = tid + t * 128;
                int r = ci >> 2, c4 = (ci & 3) * 8;
                cpa16h(Vd + r * VP2 + c4, vtb + (size_t)r * NS + kc0n + c4);
            }
            CP_COMMIT();
        }
        const __half* Kt = Kb + (jt & 1) * (32 * KP2);
        const __half* Vt = Vb + (jt & 1) * (64 * VP2);
        const int kc0 = jt * 32;

        // S = Q K^T  (warp: 16 x 32)
        float sacc[4][4] = {};
        #pragma unroll
        for (int ks = 0; ks < 4; ks++) {
            #pragma unroll
            for (int kp = 0; kp < 2; kp++) {
                unsigned b4[4];
                ldsm4h(b4, Kt + kp * 16 * KP2 + aoffK + ks * 16);
                unsigned b0[2] = {b4[0], b4[2]};
                unsigned b1[2] = {b4[1], b4[3]};
                mma16(sacc[kp * 2],     qa[ks], b0);
                mma16(sacc[kp * 2 + 1], qa[ks], b1);
            }
        }

        // scale + causal mask (only last two tiles touch the diagonal)
        const int r0 = q0 + w * 16 + g;
        if (jt >= nkt - 2) {
            #pragma unroll
            for (int nt = 0; nt < 4; nt++) {
                int col = kc0 + nt * 8 + 2 * tg;
                sacc[nt][0] = (col     <= r0    ) ? sacc[nt][0] * 0.125f : -3.0e38f;
                sacc[nt][1] = (col + 1 <= r0    ) ? sacc[nt][1] * 0.125f : -3.0e38f;
                sacc[nt][2] = (col     <= r0 + 8) ? sacc[nt][2] * 0.125f : -3.0e38f;
                sacc[nt][3] = (col + 1 <= r0 + 8) ? sacc[nt][3] * 0.125f : -3.0e38f;
            }
        } else {
            #pragma unroll
            for (int nt = 0; nt < 4; nt++) {
                sacc[nt][0] *= 0.125f; sacc[nt][1] *= 0.125f;
                sacc[nt][2] *= 0.125f; sacc[nt][3] *= 0.125f;
            }
        }

        // row max
        float mt0 = -3.0e38f, mt1 = -3.0e38f;
        #pragma unroll
        for (int nt = 0; nt < 4; nt++) {
            mt0 = fmaxf(mt0, fmaxf(sacc[nt][0], sacc[nt][1]));
            mt1 = fmaxf(mt1, fmaxf(sacc[nt][2], sacc[nt][3]));
        }
        mt0 = fmaxf(mt0, __shfl_xor_sync(0xffffffffu, mt0, 1));
        mt0 = fmaxf(mt0, __shfl_xor_sync(0xffffffffu, mt0, 2));
        mt1 = fmaxf(mt1, __shfl_xor_sync(0xffffffffu, mt1, 1));
        mt1 = fmaxf(mt1, __shfl_xor_sync(0xffffffffu, mt1, 2));

        float mn0 = fmaxf(m_i[0], mt0), mn1 = fmaxf(m_i[1], mt1);
        float al0 = __expf(m_i[0] - mn0), al1 = __expf(m_i[1] - mn1);
        m_i[0] = mn0; m_i[1] = mn1;

        const int rb0 = (w * 16 + g) * VP2;
        const int rb1 = rb0 + 8 * VP2;
        float ls0 = 0.f, ls1 = 0.f;
        #pragma unroll
        for (int nt = 0; nt < 4; nt++) {
            float p0 = __expf(sacc[nt][0] - mn0);
            float p1 = __expf(sacc[nt][1] - mn0);
            float p2 = __expf(sacc[nt][2] - mn1);
            float p3 = __expf(sacc[nt][3] - mn1);
            ls0 += p0 + p1; ls1 += p2 + p3;
            int cl = nt * 8 + 2 * tg;
            *(__half2*)&Pb[rb0 + cl] = __floats2half2_rn(p0, p1);
            *(__half2*)&Pb[rb1 + cl] = __floats2half2_rn(p2, p3);
        }
        #pragma unroll
        for (int nt = 0; nt < 8; nt++) {
            oacc[nt][0] *= al0; oacc[nt][1] *= al0;
            oacc[nt][2] *= al1; oacc[nt][3] *= al1;
        }
        ls0 += __shfl_xor_sync(0xffffffffu, ls0, 1);
        ls0 += __shfl_xor_sync(0xffffffffu, ls0, 2);
        ls1 += __shfl_xor_sync(0xffffffffu, ls1, 1);
        ls1 += __shfl_xor_sync(0xffffffffu, ls1, 2);
        l_i[0] = l_i[0] * al0 + ls0;
        l_i[1] = l_i[1] * al1 + ls1;

        __syncwarp();      // P rows warp-private

        // O += P @ V  (warp: 16 x 64, k = 32 keys = 2 k16 steps)
        #pragma unroll
        for (int ks = 0; ks < 2; ks++) {
            unsigned pa[4];
            ldsm4h(pa, Pb + (w * 16) * VP2 + aoffV + ks * 16);
            #pragma unroll
            for (int fg = 0; fg < 4; fg++) {
                unsigned b4[4];
                ldsm4h(b4, Vt + fg * 16 * VP2 + aoffV + ks * 16);
                unsigned b0[2] = {b4[0], b4[2]};
                unsigned b1[2] = {b4[1], b4[3]};
                mma16(oacc[fg * 2],     pa, b0);
                mma16(oacc[fg * 2 + 1], pa, b1);
            }
        }
    }

    // normalize + convert fp16 + write concat layout [B*S, H*DK]
    const float inv0 = 1.f / l_i[0], inv1 = 1.f / l_i[1];
    const int b_ = bh / NH, h_ = bh % NH;
    const size_t mrow = (size_t)b_ * NS + q0 + w * 16 + g;
    #pragma unroll
    for (int nt = 0; nt < 8; nt++) {
        int cc = h_ * NDK + nt * 8 + 2 * tg;
        *(__half2*)&g_cat[ mrow      * (NH * NDK) + cc] =
            __floats2half2_rn(oacc[nt][0] * inv0, oacc[nt][1] * inv0);
        *(__half2*)&g_cat[(mrow + 8) * (NH * NDK) + cc] =
            __floats2half2_rn(oacc[nt][2] * inv1, oacc[nt][3] * inv1);
    }
}

// ---------------------------------------------------------------------------
// Kernel 3: output projection. C[8192,1024] = g_cat @ Wo + bo (fp32 out).
// ---------------------------------------------------------------------------
__global__ __launch_bounds__(256, 2) void proj_kernel(
    const float* __restrict__ bo, float* __restrict__ out)
{
    extern __shared__ __align__(16) __half smh[];
    const int m0 = blockIdx.y * 128;
    const int n0 = blockIdx.x * 128;
    const int tid  = threadIdx.x;
    const int warp = tid >> 5, lane = tid & 31;
    const int g = lane >> 2, tg = lane & 3;

    HGemmCtx c;
    c.As = smh; c.Bs = smh + 2 * HST;
    c.xb = g_cat + (size_t)m0 * ND;
    c.wb = g_wot + (size_t)n0 * ND;
    c.aoff = (lane & 15) * HP + (lane >> 4) * 8;
    c.wm = warp >> 1; c.wn = warp & 1; c.tid = tid;

    float acc[2][8][4] = {};
    h_mainloop(c, acc);

    #pragma unroll
    for (int nt = 0; nt < 8; nt++) {
        int cc = c.wn * 64 + nt * 8 + 2 * tg;
        float b0 = bo[n0 + cc], b1 = bo[n0 + cc + 1];
        #pragma unroll
        for (int mt = 0; mt < 2; mt++)
            #pragma unroll
            for (int p = 0; p < 2; p++) {
                int rr = c.wm * 32 + mt * 16 + g + p * 8;
                float2 v;
                v.x = acc[mt][nt][2 * p + 0] + b0;
                v.y = acc[mt][nt][2 * p + 1] + b1;
                *(float2*)(out + (size_t)(m0 + rr) * ND + n0 + cc) = v;
            }
    }
}

// ---------------------------------------------------------------------------
extern "C" void kernel_launch(void* const* d_in, const int* in_sizes, int n_in,
                              void* d_out, int out_size)
{
    (void)in_sizes; (void)n_in; (void)out_size;
    const float* x  = (const float*)d_in[0];
    // d_in[1] = encoder_output (unused in the self-attention path)
    const float* Wq = (const float*)d_in[2];
    const float* bq = (const float*)d_in[3];
    const float* Wk = (const float*)d_in[4];
    const float* bk = (const float*)d_in[5];
    const float* Wv = (const float*)d_in[6];
    const float* bv = (const float*)d_in[7];
    const float* Wo = (const float*)d_in[8];
    const float* bo = (const float*)d_in[9];
    float* out = (float*)d_out;

    cudaFuncSetAttribute(qkv_kernel,  cudaFuncAttributeMaxDynamicSharedMemorySize, GEMM_SMEM_B);
    cudaFuncSetAttribute(proj_kernel, cudaFuncAttributeMaxDynamicSharedMemorySize, GEMM_SMEM_B);

    conv_x_kernel<<<(NBS * ND) / (256 * 8), 256>>>(x);
    pack_w_kernel<<<dim3(ND / 32, NDK / 32, NH * 3), dim3(32, 8)>>>(Wq, Wk, Wv);
    pack_wo_kernel<<<dim3(ND / 32, ND / 32), dim3(32, 8)>>>(Wo);
    qkv_kernel<<<dim3(NBS / 128, (NH * 3 * NDK) / 128), 256, GEMM_SMEM_B>>>(bq, bk, bv);
    attn_kernel<<<dim3(NS / 64, NB * NH), 128>>>();
    proj_kernel<<<dim3(ND / 128, NBS / 128), 256, GEMM_SMEM_B>>>(bo, out);
}